// round 2
// baseline (speedup 1.0000x reference)
#include <cuda_runtime.h>
#include <cstdint>

// ---------------------------------------------------------------------------
// SESConv_H_H: scale-equivariant grouped conv, direct fp32 implementation.
//
//   out[b,o,g,h,w] = sum_{ij,c,xy} Keff[g,ij,o,c,xy] * x[b,c,s'(g,ij),h+x-2,w+y-2]
//   Keff[g,ij,o,c,xy] = sum_f weight[o,c,ij,f] * basis[f,g,xy]
//   s'(g=(nr,ns), ij=(i,j)) = ((nr+i)&3)*3 + (ns+j),  skipped if ns+j >= 3
// ---------------------------------------------------------------------------

#define NRg   4
#define NSg   3
#define SG    12      // NR*NS
#define CIN   16
#define COUT  16
#define BATCH 8
#define HWD   128
#define NFb   9
#define KPAD  28      // 5*5 = 25 taps padded to 28 for float4 loads
#define KSLICE (COUT * KPAD)   // 448 floats per (g,ij,c) slice

#define TILE_W 8
#define TILE_H 16
#define HALO_W 12     // TILE_W + 4
#define HALO_H 20     // TILE_H + 4
#define HALO_N (HALO_W * HALO_H)   // 240

// Precomputed effective kernels: [g][ij][c][o][KPAD]  (1.31 MB)
__device__ float g_keff[SG * 4 * CIN * KSLICE];

__global__ void build_keff_kernel(const float* __restrict__ weight,
                                  const float* __restrict__ basis) {
    const int total = SG * 4 * CIN * COUT * KPAD;
    int idx = blockIdx.x * blockDim.x + threadIdx.x;
    if (idx >= total) return;
    int t    = idx % KPAD;
    int rest = idx / KPAD;
    int o  = rest % COUT; rest /= COUT;
    int c  = rest % CIN;  rest /= CIN;
    int ij = rest % 4;
    int g  = rest / 4;
    float v = 0.f;
    if (t < 25) {
#pragma unroll
        for (int f = 0; f < NFb; ++f)
            v += weight[((o * CIN + c) * 4 + ij) * NFb + f] *
                 basis[(f * SG + g) * 25 + t];
    }
    g_keff[idx] = v;
}

__device__ __forceinline__ void load_plane(const float* __restrict__ x,
                                           int b, int nr, int ns, int g,
                                           int ij, int c,
                                           int ty0, int tx0, int tid,
                                           float* __restrict__ xdst,
                                           float* __restrict__ kdst) {
    const int i = ij >> 1;
    const int j = ij & 1;
    const int sp = ((nr + i) & 3) * NSg + (ns + j);
    const float* xp = x + ((((size_t)b * CIN + c) * SG + sp) << 14);
    if (tid < HALO_N) {
        const int r  = tid / HALO_W;
        const int cc = tid - r * HALO_W;
        const int gy = ty0 + r - 2;
        const int gx = tx0 + cc - 2;
        float v = 0.f;
        if ((unsigned)gy < (unsigned)HWD && (unsigned)gx < (unsigned)HWD)
            v = __ldg(xp + gy * HWD + gx);
        xdst[tid] = v;
    }
    const float* kp = g_keff + (size_t)((g * 4 + ij) * CIN + c) * KSLICE;
    for (int idx = tid; idx < KSLICE; idx += 256)
        kdst[idx] = kp[idx];
}

__global__ void __launch_bounds__(256, 2)
ses_main_kernel(const float* __restrict__ x, float* __restrict__ out) {
    __shared__ float xsm[2][HALO_N];
    __shared__ float ksm[2][KSLICE];

    const int tid   = threadIdx.x;
    const int o     = tid & 15;    // output channel
    const int strip = tid >> 4;    // output row within tile (0..15)

    const int bz = blockIdx.z;
    const int b  = bz / SG;
    const int g  = bz % SG;
    const int nr = g / NSg;
    const int ns = g % NSg;
    const int tx0 = blockIdx.x * TILE_W;
    const int ty0 = blockIdx.y * TILE_H;

    // valid (i,j) shift list (skip zero-padded scale shifts)
    int ijv[4];
    int nv = 0;
#pragma unroll
    for (int ij = 0; ij < 4; ++ij)
        if (ns + (ij & 1) < NSg) ijv[nv++] = ij;
    const int nplanes = nv * CIN;

    float acc[8];
#pragma unroll
    for (int p = 0; p < 8; ++p) acc[p] = 0.f;

    // prime double buffer
    load_plane(x, b, nr, ns, g, ijv[0], 0, ty0, tx0, tid, xsm[0], ksm[0]);
    __syncthreads();

    for (int p = 0; p < nplanes; ++p) {
        const int buf = p & 1;
        if (p + 1 < nplanes) {
            const int pn = p + 1;
            load_plane(x, b, nr, ns, g, ijv[pn >> 4], pn & 15,
                       ty0, tx0, tid, xsm[buf ^ 1], ksm[buf ^ 1]);
        }

        // per-thread kernel taps (vectorized SMEM loads, 112B-aligned)
        float kk[KPAD];
        {
            float4* kkv = reinterpret_cast<float4*>(kk);
            const float4* kp4 =
                reinterpret_cast<const float4*>(&ksm[buf][o * KPAD]);
#pragma unroll
            for (int q = 0; q < KPAD / 4; ++q) kkv[q] = kp4[q];
        }

#pragma unroll
        for (int ky = 0; ky < 5; ++ky) {
            float xv[12];
            {
                float4* xvv = reinterpret_cast<float4*>(xv);
                const float4* xr4 = reinterpret_cast<const float4*>(
                    &xsm[buf][(strip + ky) * HALO_W]);
#pragma unroll
                for (int q = 0; q < 3; ++q) xvv[q] = xr4[q];
            }
#pragma unroll
            for (int kx = 0; kx < 5; ++kx) {
                const float kv = kk[ky * 5 + kx];
#pragma unroll
                for (int px = 0; px < 8; ++px)
                    acc[px] = fmaf(xv[px + kx], kv, acc[px]);
            }
        }
        __syncthreads();
    }

    // store 8 contiguous outputs for (b, o, g, ty0+strip, tx0..tx0+7)
    float* op = out + ((((size_t)b * COUT + o) * SG + g) << 14) +
                (size_t)(ty0 + strip) * HWD + tx0;
    float4 v0 = make_float4(acc[0], acc[1], acc[2], acc[3]);
    float4 v1 = make_float4(acc[4], acc[5], acc[6], acc[7]);
    *reinterpret_cast<float4*>(op)     = v0;
    *reinterpret_cast<float4*>(op + 4) = v1;
}

extern "C" void kernel_launch(void* const* d_in, const int* in_sizes, int n_in,
                              void* d_out, int out_size) {
    const float* x      = (const float*)d_in[0];
    const float* weight = (const float*)d_in[1];
    const float* basis  = (const float*)d_in[2];
    float* out = (float*)d_out;

    const int total = SG * 4 * CIN * COUT * KPAD;
    build_keff_kernel<<<(total + 255) / 256, 256>>>(weight, basis);

    dim3 grid(HWD / TILE_W, HWD / TILE_H, BATCH * SG);
    ses_main_kernel<<<grid, 256>>>(x, out);
}

// round 3
// speedup vs baseline: 1.2956x; 1.2956x over previous
#include <cuda_runtime.h>
#include <cstdint>

// ---------------------------------------------------------------------------
// SESConv_H_H — fp32 direct conv using packed fma.rn.f32x2 (FFMA2).
// Pairing axis: 2 adjacent output channels per thread, so the filter operand
// is a natural 64-bit register pair (zero packing cost); only x needs dup.
// ---------------------------------------------------------------------------

#define NSg   3
#define SG    12
#define CIN   16
#define COUT  16
#define BATCH 8
#define HWD   128

#define TILE_W 8
#define TILE_H 32
#define HALO_W 12                 // TILE_W + 4
#define HALO_H 36                 // TILE_H + 4
#define HALO_N (HALO_W * HALO_H)  // 432

// Keff layout per (g,ij,c) slice: [opair(8)][ky(5)][12]  (kx*2+par in 0..9, 2 pad)
#define KROW   12
#define KSLICE (8 * 5 * KROW)     // 480 floats

__device__ float g_keff[SG * 4 * CIN * KSLICE];

typedef unsigned long long u64;

__device__ __forceinline__ u64 dup2(float a) {
    u64 r;
    asm("mov.b64 %0, {%1,%1};" : "=l"(r) : "f"(a));
    return r;
}
__device__ __forceinline__ void fma2(u64& d, u64 a, u64 b) {
    asm("fma.rn.f32x2 %0, %1, %2, %0;" : "+l"(d) : "l"(a), "l"(b));
}
__device__ __forceinline__ void unpack2(u64 v, float& lo, float& hi) {
    asm("mov.b64 {%0,%1}, %2;" : "=f"(lo), "=f"(hi) : "l"(v));
}

__global__ void build_keff_kernel(const float* __restrict__ weight,
                                  const float* __restrict__ basis) {
    const int total = SG * 4 * CIN * COUT * 25;
    int idx = blockIdx.x * blockDim.x + threadIdx.x;
    if (idx >= total) return;
    int tap  = idx % 25;
    int rest = idx / 25;
    int o  = rest % COUT; rest /= COUT;
    int c  = rest % CIN;  rest /= CIN;
    int ij = rest % 4;
    int g  = rest / 4;
    float v = 0.f;
#pragma unroll
    for (int f = 0; f < 9; ++f)
        v += weight[((o * CIN + c) * 4 + ij) * 9 + f] *
             basis[(f * SG + g) * 25 + tap];
    const int ky = tap / 5, kx = tap % 5;
    g_keff[(size_t)((g * 4 + ij) * CIN + c) * KSLICE +
           (o >> 1) * (5 * KROW) + ky * KROW + kx * 2 + (o & 1)] = v;
}

__device__ __forceinline__ void load_plane(const float* __restrict__ x,
                                           int b, int nr, int ns, int g,
                                           int ij, int c,
                                           int ty0, int tx0, int tid,
                                           float* __restrict__ xdst,
                                           float* __restrict__ kdst) {
    const int i = ij >> 1;
    const int j = ij & 1;
    const int sp = ((nr + i) & 3) * NSg + (ns + j);
    const float* xp = x + ((((size_t)b * CIN + c) * SG + sp) << 14);
#pragma unroll
    for (int t = tid; t < HALO_N; t += 256) {
        const int r  = t / HALO_W;
        const int cc = t - r * HALO_W;
        const int gy = ty0 + r - 2;
        const int gx = tx0 + cc - 2;
        float v = 0.f;
        if ((unsigned)gy < (unsigned)HWD && (unsigned)gx < (unsigned)HWD)
            v = __ldg(xp + gy * HWD + gx);
        xdst[t] = v;
    }
    const float* kp = g_keff + (size_t)((g * 4 + ij) * CIN + c) * KSLICE;
#pragma unroll
    for (int t = tid; t < KSLICE; t += 256)
        kdst[t] = kp[t];
}

__global__ void __launch_bounds__(256, 3)
ses_main_kernel(const float* __restrict__ x, float* __restrict__ out) {
    __shared__ __align__(16) float xsm[2][HALO_N];
    __shared__ __align__(16) float ksm[2][KSLICE];

    const int tid   = threadIdx.x;
    const int opair = tid & 7;     // output-channel pair (o = 2*opair, 2*opair+1)
    const int strip = tid >> 3;    // output row within tile (0..31)

    const int bz = blockIdx.z;
    const int b  = bz / SG;
    const int g  = bz % SG;
    const int nr = g / NSg;
    const int ns = g % NSg;
    const int tx0 = blockIdx.x * TILE_W;
    const int ty0 = blockIdx.y * TILE_H;

    int ijv[4];
    int nv = 0;
#pragma unroll
    for (int ij = 0; ij < 4; ++ij)
        if (ns + (ij & 1) < NSg) ijv[nv++] = ij;
    const int nplanes = nv * CIN;

    u64 acc[8];
#pragma unroll
    for (int p = 0; p < 8; ++p) acc[p] = 0ull;

    load_plane(x, b, nr, ns, g, ijv[0], 0, ty0, tx0, tid, xsm[0], ksm[0]);
    __syncthreads();

    for (int p = 0; p < nplanes; ++p) {
        const int buf = p & 1;
        if (p + 1 < nplanes) {
            const int pn = p + 1;
            load_plane(x, b, nr, ns, g, ijv[pn >> 4], pn & 15,
                       ty0, tx0, tid, xsm[buf ^ 1], ksm[buf ^ 1]);
        }

        const float* kbase = &ksm[buf][opair * (5 * KROW)];

#pragma unroll
        for (int ky = 0; ky < 5; ++ky) {
            // x row: 12 floats, duplicated into (x,x) register pairs
            float xv[12];
            {
                float4* xvv = reinterpret_cast<float4*>(xv);
                const float4* xr4 = reinterpret_cast<const float4*>(
                    &xsm[buf][(strip + ky) * HALO_W]);
#pragma unroll
                for (int q = 0; q < 3; ++q) xvv[q] = xr4[q];
            }
            u64 xd[12];
#pragma unroll
            for (int q = 0; q < 12; ++q) xd[q] = dup2(xv[q]);

            // k row: 5 natural (o0,o1) pairs, vector-loaded
            const float* kr = kbase + ky * KROW;
            ulonglong2 kA = *reinterpret_cast<const ulonglong2*>(kr);
            ulonglong2 kB = *reinterpret_cast<const ulonglong2*>(kr + 4);
            u64 kk0 = kA.x, kk1 = kA.y, kk2 = kB.x, kk3 = kB.y;
            u64 kk4 = *reinterpret_cast<const u64*>(kr + 8);

#pragma unroll
            for (int px = 0; px < 8; ++px) fma2(acc[px], xd[px + 0], kk0);
#pragma unroll
            for (int px = 0; px < 8; ++px) fma2(acc[px], xd[px + 1], kk1);
#pragma unroll
            for (int px = 0; px < 8; ++px) fma2(acc[px], xd[px + 2], kk2);
#pragma unroll
            for (int px = 0; px < 8; ++px) fma2(acc[px], xd[px + 3], kk3);
#pragma unroll
            for (int px = 0; px < 8; ++px) fma2(acc[px], xd[px + 4], kk4);
        }
        __syncthreads();
    }

    // unpack and store: o0 = 2*opair (low halves), o1 = 2*opair+1 (high halves)
    float lo[8], hi[8];
#pragma unroll
    for (int px = 0; px < 8; ++px) unpack2(acc[px], lo[px], hi[px]);

    const size_t row_off = (size_t)(ty0 + strip) * HWD + tx0;
    float* op0 = out + ((((size_t)b * COUT + 2 * opair)     * SG + g) << 14) + row_off;
    float* op1 = out + ((((size_t)b * COUT + 2 * opair + 1) * SG + g) << 14) + row_off;
    reinterpret_cast<float4*>(op0)[0] = make_float4(lo[0], lo[1], lo[2], lo[3]);
    reinterpret_cast<float4*>(op0)[1] = make_float4(lo[4], lo[5], lo[6], lo[7]);
    reinterpret_cast<float4*>(op1)[0] = make_float4(hi[0], hi[1], hi[2], hi[3]);
    reinterpret_cast<float4*>(op1)[1] = make_float4(hi[4], hi[5], hi[6], hi[7]);
}

extern "C" void kernel_launch(void* const* d_in, const int* in_sizes, int n_in,
                              void* d_out, int out_size) {
    const float* x      = (const float*)d_in[0];
    const float* weight = (const float*)d_in[1];
    const float* basis  = (const float*)d_in[2];
    float* out = (float*)d_out;

    const int total = SG * 4 * CIN * COUT * 25;
    build_keff_kernel<<<(total + 255) / 256, 256>>>(weight, basis);

    dim3 grid(HWD / TILE_W, HWD / TILE_H, BATCH * SG);
    ses_main_kernel<<<grid, 256>>>(x, out);
}

// round 4
// speedup vs baseline: 1.3353x; 1.0306x over previous
#include <cuda_runtime.h>
#include <cstdint>

// ---------------------------------------------------------------------------
// SESConv_H_H — fp32 direct conv, packed fma.rn.f32x2 (FFMA2).
// R3: software-pipelined LDG->regs prefetch (decoupled from STS) and
// 2-plane stages to halve barriers. Compute core unchanged from R2.
// ---------------------------------------------------------------------------

#define NSg   3
#define SG    12
#define CIN   16
#define COUT  16
#define BATCH 8
#define HWD   128

#define TILE_W 8
#define TILE_H 32
#define HALO_W 12                 // TILE_W + 4
#define HALO_H 36                 // TILE_H + 4
#define HALO_N (HALO_W * HALO_H)  // 432

#define KROW   12
#define KSLICE (8 * 5 * KROW)     // 480 floats per (g,ij,c) slice

__device__ float g_keff[SG * 4 * CIN * KSLICE];

typedef unsigned long long u64;

__device__ __forceinline__ u64 dup2(float a) {
    u64 r;
    asm("mov.b64 %0, {%1,%1};" : "=l"(r) : "f"(a));
    return r;
}
__device__ __forceinline__ void fma2(u64& d, u64 a, u64 b) {
    asm("fma.rn.f32x2 %0, %1, %2, %0;" : "+l"(d) : "l"(a), "l"(b));
}
__device__ __forceinline__ void unpack2(u64 v, float& lo, float& hi) {
    asm("mov.b64 {%0,%1}, %2;" : "=f"(lo), "=f"(hi) : "l"(v));
}

__global__ void build_keff_kernel(const float* __restrict__ weight,
                                  const float* __restrict__ basis) {
    const int total = SG * 4 * CIN * COUT * 25;
    int idx = blockIdx.x * blockDim.x + threadIdx.x;
    if (idx >= total) return;
    int tap  = idx % 25;
    int rest = idx / 25;
    int o  = rest % COUT; rest /= COUT;
    int c  = rest % CIN;  rest /= CIN;
    int ij = rest % 4;
    int g  = rest / 4;
    float v = 0.f;
#pragma unroll
    for (int f = 0; f < 9; ++f)
        v += weight[((o * CIN + c) * 4 + ij) * 9 + f] *
             basis[(f * SG + g) * 25 + tap];
    const int ky = tap / 5, kx = tap % 5;
    g_keff[(size_t)((g * 4 + ij) * CIN + c) * KSLICE +
           (o >> 1) * (5 * KROW) + ky * KROW + kx * 2 + (o & 1)] = v;
}

// ---- stage = 2 consecutive planes ------------------------------------------
// x: 2*HALO_N = 864 elems, k: 2*KSLICE = 960 elems, over 256 threads -> 4 regs each.

__device__ __forceinline__ void ldg_stage(const float* __restrict__ x,
                                          int b, int nr, int ns, int g,
                                          const int* ijv, int p0,
                                          int ty0, int tx0, int tid,
                                          float xr[4], float kr[4]) {
    // plane bases for p0 and p0+1
    const float* xp[2];
    const float* kp[2];
#pragma unroll
    for (int q = 0; q < 2; ++q) {
        const int pl = p0 + q;
        const int ij = ijv[pl >> 4];
        const int c  = pl & 15;
        const int sp = ((nr + (ij >> 1)) & 3) * NSg + (ns + (ij & 1));
        xp[q] = x + ((((size_t)b * CIN + c) * SG + sp) << 14);
        kp[q] = g_keff + (size_t)((g * 4 + ij) * CIN + c) * KSLICE;
    }
#pragma unroll
    for (int q = 0; q < 4; ++q) {
        const int e = tid + q * 256;
        float v = 0.f;
        if (e < 2 * HALO_N) {
            const int pl = (e >= HALO_N);
            const int t  = e - (pl ? HALO_N : 0);
            const int r  = t / HALO_W;
            const int cc = t - r * HALO_W;
            const int gy = ty0 + r - 2;
            const int gx = tx0 + cc - 2;
            if ((unsigned)gy < (unsigned)HWD && (unsigned)gx < (unsigned)HWD)
                v = __ldg(xp[pl] + gy * HWD + gx);
        }
        xr[q] = v;
    }
#pragma unroll
    for (int q = 0; q < 4; ++q) {
        const int e = tid + q * 256;
        if (e < 2 * KSLICE) {
            const int pl = (e >= KSLICE);
            kr[q] = __ldg(kp[pl] + (e - (pl ? KSLICE : 0)));
        } else {
            kr[q] = 0.f;
        }
    }
}

__device__ __forceinline__ void sts_stage(int tid,
                                          const float xr[4], const float kr[4],
                                          float* __restrict__ xdst,
                                          float* __restrict__ kdst) {
#pragma unroll
    for (int q = 0; q < 4; ++q) {
        const int e = tid + q * 256;
        if (e < 2 * HALO_N) xdst[e] = xr[q];
    }
#pragma unroll
    for (int q = 0; q < 4; ++q) {
        const int e = tid + q * 256;
        if (e < 2 * KSLICE) kdst[e] = kr[q];
    }
}

__device__ __forceinline__ void compute_plane(const float* __restrict__ xbase,
                                              const float* __restrict__ kbase,
                                              int strip, u64 acc[8]) {
#pragma unroll
    for (int ky = 0; ky < 5; ++ky) {
        float xv[12];
        {
            float4* xvv = reinterpret_cast<float4*>(xv);
            const float4* xr4 = reinterpret_cast<const float4*>(
                &xbase[(strip + ky) * HALO_W]);
#pragma unroll
            for (int q = 0; q < 3; ++q) xvv[q] = xr4[q];
        }
        u64 xd[12];
#pragma unroll
        for (int q = 0; q < 12; ++q) xd[q] = dup2(xv[q]);

        const float* kr = kbase + ky * KROW;
        ulonglong2 kA = *reinterpret_cast<const ulonglong2*>(kr);
        ulonglong2 kB = *reinterpret_cast<const ulonglong2*>(kr + 4);
        u64 kk0 = kA.x, kk1 = kA.y, kk2 = kB.x, kk3 = kB.y;
        u64 kk4 = *reinterpret_cast<const u64*>(kr + 8);

#pragma unroll
        for (int px = 0; px < 8; ++px) fma2(acc[px], xd[px + 0], kk0);
#pragma unroll
        for (int px = 0; px < 8; ++px) fma2(acc[px], xd[px + 1], kk1);
#pragma unroll
        for (int px = 0; px < 8; ++px) fma2(acc[px], xd[px + 2], kk2);
#pragma unroll
        for (int px = 0; px < 8; ++px) fma2(acc[px], xd[px + 3], kk3);
#pragma unroll
        for (int px = 0; px < 8; ++px) fma2(acc[px], xd[px + 4], kk4);
    }
}

__global__ void __launch_bounds__(256, 3)
ses_main_kernel(const float* __restrict__ x, float* __restrict__ out) {
    // stage buffers: 2 planes each, double-buffered
    __shared__ __align__(16) float xsm[2][2 * HALO_N];
    __shared__ __align__(16) float ksm[2][2 * KSLICE];

    const int tid   = threadIdx.x;
    const int opair = tid & 7;     // o = 2*opair, 2*opair+1
    const int strip = tid >> 3;    // output row within tile (0..31)

    const int bz = blockIdx.z;
    const int b  = bz / SG;
    const int g  = bz % SG;
    const int nr = g / NSg;
    const int ns = g % NSg;
    const int tx0 = blockIdx.x * TILE_W;
    const int ty0 = blockIdx.y * TILE_H;

    int ijv[4];
    int nv = 0;
#pragma unroll
    for (int ij = 0; ij < 4; ++ij)
        if (ns + (ij & 1) < NSg) ijv[nv++] = ij;
    const int nstages = (nv * CIN) >> 1;   // 2 planes per stage (16 or 32)

    u64 acc[8];
#pragma unroll
    for (int p = 0; p < 8; ++p) acc[p] = 0ull;

    float xr[4], kr[4];
    // prologue: stage 0
    ldg_stage(x, b, nr, ns, g, ijv, 0, ty0, tx0, tid, xr, kr);
    sts_stage(tid, xr, kr, xsm[0], ksm[0]);
    __syncthreads();

    for (int s = 0; s < nstages; ++s) {
        const int buf = s & 1;
        const bool more = (s + 1 < nstages);
        if (more)   // issue LDGs now; latency hidden under compute below
            ldg_stage(x, b, nr, ns, g, ijv, 2 * (s + 1), ty0, tx0, tid, xr, kr);

        compute_plane(&xsm[buf][0],
                      &ksm[buf][opair * (5 * KROW)], strip, acc);
        compute_plane(&xsm[buf][HALO_N],
                      &ksm[buf][KSLICE + opair * (5 * KROW)], strip, acc);

        if (more)   // LDG data has arrived by now; cheap STS
            sts_stage(tid, xr, kr, xsm[buf ^ 1], ksm[buf ^ 1]);
        __syncthreads();
    }

    float lo[8], hi[8];
#pragma unroll
    for (int px = 0; px < 8; ++px) unpack2(acc[px], lo[px], hi[px]);

    const size_t row_off = (size_t)(ty0 + strip) * HWD + tx0;
    float* op0 = out + ((((size_t)b * COUT + 2 * opair)     * SG + g) << 14) + row_off;
    float* op1 = out + ((((size_t)b * COUT + 2 * opair + 1) * SG + g) << 14) + row_off;
    reinterpret_cast<float4*>(op0)[0] = make_float4(lo[0], lo[1], lo[2], lo[3]);
    reinterpret_cast<float4*>(op0)[1] = make_float4(lo[4], lo[5], lo[6], lo[7]);
    reinterpret_cast<float4*>(op1)[0] = make_float4(hi[0], hi[1], hi[2], hi[3]);
    reinterpret_cast<float4*>(op1)[1] = make_float4(hi[4], hi[5], hi[6], hi[7]);
}

extern "C" void kernel_launch(void* const* d_in, const int* in_sizes, int n_in,
                              void* d_out, int out_size) {
    const float* x      = (const float*)d_in[0];
    const float* weight = (const float*)d_in[1];
    const float* basis  = (const float*)d_in[2];
    float* out = (float*)d_out;

    const int total = SG * 4 * CIN * COUT * 25;
    build_keff_kernel<<<(total + 255) / 256, 256>>>(weight, basis);

    dim3 grid(HWD / TILE_W, HWD / TILE_H, BATCH * SG);
    ses_main_kernel<<<grid, 256>>>(x, out);
}

// round 5
// speedup vs baseline: 1.4332x; 1.0733x over previous
#include <cuda_runtime.h>
#include <cstdint>

// ---------------------------------------------------------------------------
// SESConv_H_H — fp32 direct conv, packed fma.rn.f32x2 (FFMA2).
// R4: 2 output rows per thread (row reuse cuts LDS/dup traffic 40%),
// rotating k-row registers, pipelined LDG prefetch from R3.
// ---------------------------------------------------------------------------

#define NSg   3
#define SG    12
#define CIN   16
#define COUT  16
#define BATCH 8
#define HWD   128

#define TILE_W 8
#define TILE_H 64                 // 32 double-strips of 2 rows
#define HALO_W 12                 // TILE_W + 4
#define HALO_H 68                 // TILE_H + 4
#define HALO_N (HALO_W * HALO_H)  // 816

#define KROW   12
#define KSLICE (8 * 5 * KROW)     // 480 floats per (g,ij,c) slice

#define XSTAGE (2 * HALO_N)       // 1632 floats (2 planes)
#define KSTAGE (2 * KSLICE)       // 960  floats (2 planes)

__device__ float g_keff[SG * 4 * CIN * KSLICE];

typedef unsigned long long u64;

__device__ __forceinline__ u64 dup2(float a) {
    u64 r;
    asm("mov.b64 %0, {%1,%1};" : "=l"(r) : "f"(a));
    return r;
}
__device__ __forceinline__ void fma2(u64& d, u64 a, u64 b) {
    asm("fma.rn.f32x2 %0, %1, %2, %0;" : "+l"(d) : "l"(a), "l"(b));
}
__device__ __forceinline__ void unpack2(u64 v, float& lo, float& hi) {
    asm("mov.b64 {%0,%1}, %2;" : "=f"(lo), "=f"(hi) : "l"(v));
}

__global__ void build_keff_kernel(const float* __restrict__ weight,
                                  const float* __restrict__ basis) {
    const int total = SG * 4 * CIN * COUT * 25;
    int idx = blockIdx.x * blockDim.x + threadIdx.x;
    if (idx >= total) return;
    int tap  = idx % 25;
    int rest = idx / 25;
    int o  = rest % COUT; rest /= COUT;
    int c  = rest % CIN;  rest /= CIN;
    int ij = rest % 4;
    int g  = rest / 4;
    float v = 0.f;
#pragma unroll
    for (int f = 0; f < 9; ++f)
        v += weight[((o * CIN + c) * 4 + ij) * 9 + f] *
             basis[(f * SG + g) * 25 + tap];
    const int ky = tap / 5, kx = tap % 5;
    g_keff[(size_t)((g * 4 + ij) * CIN + c) * KSLICE +
           (o >> 1) * (5 * KROW) + ky * KROW + kx * 2 + (o & 1)] = v;
}

// ---- staged LDG->regs prefetch (2 planes per stage) -------------------------

__device__ __forceinline__ void ldg_stage(const float* __restrict__ x,
                                          int b, int nr, int ns, int g,
                                          const int* ijv, int p0,
                                          int ty0, int tx0, int tid,
                                          float xr[7], float kr[4]) {
    const float* xp[2];
    const float* kp[2];
#pragma unroll
    for (int q = 0; q < 2; ++q) {
        const int pl = p0 + q;
        const int ij = ijv[pl >> 4];
        const int c  = pl & 15;
        const int sp = ((nr + (ij >> 1)) & 3) * NSg + (ns + (ij & 1));
        xp[q] = x + ((((size_t)b * CIN + c) * SG + sp) << 14);
        kp[q] = g_keff + (size_t)((g * 4 + ij) * CIN + c) * KSLICE;
    }
#pragma unroll
    for (int q = 0; q < 7; ++q) {
        const int e = tid + q * 256;
        float v = 0.f;
        if (e < XSTAGE) {
            const int pl = (e >= HALO_N);
            const int t  = e - (pl ? HALO_N : 0);
            const int r  = t / HALO_W;
            const int cc = t - r * HALO_W;
            const int gy = ty0 + r - 2;
            const int gx = tx0 + cc - 2;
            if ((unsigned)gy < (unsigned)HWD && (unsigned)gx < (unsigned)HWD)
                v = __ldg(xp[pl] + gy * HWD + gx);
        }
        xr[q] = v;
    }
#pragma unroll
    for (int q = 0; q < 4; ++q) {
        const int e = tid + q * 256;
        if (e < KSTAGE) {
            const int pl = (e >= KSLICE);
            kr[q] = __ldg(kp[pl] + (e - (pl ? KSLICE : 0)));
        } else {
            kr[q] = 0.f;
        }
    }
}

__device__ __forceinline__ void sts_stage(int tid,
                                          const float xr[7], const float kr[4],
                                          float* __restrict__ xdst,
                                          float* __restrict__ kdst) {
#pragma unroll
    for (int q = 0; q < 7; ++q) {
        const int e = tid + q * 256;
        if (e < XSTAGE) xdst[e] = xr[q];
    }
#pragma unroll
    for (int q = 0; q < 4; ++q) {
        const int e = tid + q * 256;
        if (e < KSTAGE) kdst[e] = kr[q];
    }
}

// ---- compute: one plane, 2 output rows per thread ---------------------------

__device__ __forceinline__ void dup_row(const float* __restrict__ src,
                                        u64 xd[12]) {
    float xv[12];
    float4* xvv = reinterpret_cast<float4*>(xv);
    const float4* s4 = reinterpret_cast<const float4*>(src);
#pragma unroll
    for (int q = 0; q < 3; ++q) xvv[q] = s4[q];
#pragma unroll
    for (int q = 0; q < 12; ++q) xd[q] = dup2(xv[q]);
}

__device__ __forceinline__ void load_krow(const float* __restrict__ kr,
                                          u64 kk[5]) {
    ulonglong2 kA = *reinterpret_cast<const ulonglong2*>(kr);
    ulonglong2 kB = *reinterpret_cast<const ulonglong2*>(kr + 4);
    kk[0] = kA.x; kk[1] = kA.y; kk[2] = kB.x; kk[3] = kB.y;
    kk[4] = *reinterpret_cast<const u64*>(kr + 8);
}

__device__ __forceinline__ void apply_row(u64 acc[8], const u64 xd[12],
                                          const u64 kk[5]) {
#pragma unroll
    for (int kx = 0; kx < 5; ++kx)
#pragma unroll
        for (int px = 0; px < 8; ++px)
            fma2(acc[px], xd[px + kx], kk[kx]);
}

__device__ __forceinline__ void compute_plane2(const float* __restrict__ xbase,
                                               const float* __restrict__ kbase,
                                               int r0, u64 acc0[8], u64 acc1[8]) {
    u64 xd[12];
    u64 kkA[5], kkB[5];

    load_krow(kbase, kkA);                         // k row 0
    dup_row(xbase + r0 * HALO_W, xd);              // halo row r0
    apply_row(acc0, xd, kkA);

#pragma unroll
    for (int q = 1; q <= 4; ++q) {
        u64* kc = (q & 1) ? kkB : kkA;             // k row q
        u64* kp = (q & 1) ? kkA : kkB;             // k row q-1
        load_krow(kbase + q * KROW, kc);
        dup_row(xbase + (r0 + q) * HALO_W, xd);
        apply_row(acc0, xd, kc);
        apply_row(acc1, xd, kp);
    }
    dup_row(xbase + (r0 + 5) * HALO_W, xd);        // halo row r0+5
    apply_row(acc1, xd, kkA);                      // k row 4 lives in kkA
}

__global__ void __launch_bounds__(256, 2)
ses_main_kernel(const float* __restrict__ x, float* __restrict__ out) {
    __shared__ __align__(16) float xsm[2][XSTAGE];
    __shared__ __align__(16) float ksm[2][KSTAGE];

    const int tid    = threadIdx.x;
    const int opair  = tid & 7;     // o = 2*opair, 2*opair+1
    const int dstrip = tid >> 3;    // double-strip: out rows 2d, 2d+1 (0..31)
    const int r0     = 2 * dstrip;  // first halo row used

    const int bz = blockIdx.z;
    const int b  = bz / SG;
    const int g  = bz % SG;
    const int nr = g / NSg;
    const int ns = g % NSg;
    const int tx0 = blockIdx.x * TILE_W;
    const int ty0 = blockIdx.y * TILE_H;

    int ijv[4];
    int nv = 0;
#pragma unroll
    for (int ij = 0; ij < 4; ++ij)
        if (ns + (ij & 1) < NSg) ijv[nv++] = ij;
    const int nstages = (nv * CIN) >> 1;

    u64 acc0[8], acc1[8];
#pragma unroll
    for (int p = 0; p < 8; ++p) { acc0[p] = 0ull; acc1[p] = 0ull; }

    float xr[7], kr[4];
    ldg_stage(x, b, nr, ns, g, ijv, 0, ty0, tx0, tid, xr, kr);
    sts_stage(tid, xr, kr, xsm[0], ksm[0]);
    __syncthreads();

    for (int s = 0; s < nstages; ++s) {
        const int buf = s & 1;
        const bool more = (s + 1 < nstages);
        if (more)
            ldg_stage(x, b, nr, ns, g, ijv, 2 * (s + 1), ty0, tx0, tid, xr, kr);

        compute_plane2(&xsm[buf][0],
                       &ksm[buf][opair * (5 * KROW)], r0, acc0, acc1);
        compute_plane2(&xsm[buf][HALO_N],
                       &ksm[buf][KSLICE + opair * (5 * KROW)], r0, acc0, acc1);

        if (more)
            sts_stage(tid, xr, kr, xsm[buf ^ 1], ksm[buf ^ 1]);
        __syncthreads();
    }

    // stores: 2 rows x 2 output channels x 8 pixels
    float lo0[8], hi0[8], lo1[8], hi1[8];
#pragma unroll
    for (int px = 0; px < 8; ++px) {
        unpack2(acc0[px], lo0[px], hi0[px]);
        unpack2(acc1[px], lo1[px], hi1[px]);
    }

    const size_t row0 = (size_t)(ty0 + r0) * HWD + tx0;
    float* op0 = out + ((((size_t)b * COUT + 2 * opair)     * SG + g) << 14) + row0;
    float* op1 = out + ((((size_t)b * COUT + 2 * opair + 1) * SG + g) << 14) + row0;
    reinterpret_cast<float4*>(op0)[0]       = make_float4(lo0[0], lo0[1], lo0[2], lo0[3]);
    reinterpret_cast<float4*>(op0)[1]       = make_float4(lo0[4], lo0[5], lo0[6], lo0[7]);
    reinterpret_cast<float4*>(op0 + HWD)[0] = make_float4(lo1[0], lo1[1], lo1[2], lo1[3]);
    reinterpret_cast<float4*>(op0 + HWD)[1] = make_float4(lo1[4], lo1[5], lo1[6], lo1[7]);
    reinterpret_cast<float4*>(op1)[0]       = make_float4(hi0[0], hi0[1], hi0[2], hi0[3]);
    reinterpret_cast<float4*>(op1)[1]       = make_float4(hi0[4], hi0[5], hi0[6], hi0[7]);
    reinterpret_cast<float4*>(op1 + HWD)[0] = make_float4(hi1[0], hi1[1], hi1[2], hi1[3]);
    reinterpret_cast<float4*>(op1 + HWD)[1] = make_float4(hi1[4], hi1[5], hi1[6], hi1[7]);
}

extern "C" void kernel_launch(void* const* d_in, const int* in_sizes, int n_in,
                              void* d_out, int out_size) {
    const float* x      = (const float*)d_in[0];
    const float* weight = (const float*)d_in[1];
    const float* basis  = (const float*)d_in[2];
    float* out = (float*)d_out;

    const int total = SG * 4 * CIN * COUT * 25;
    build_keff_kernel<<<(total + 255) / 256, 256>>>(weight, basis);

    dim3 grid(HWD / TILE_W, HWD / TILE_H, BATCH * SG);
    ses_main_kernel<<<grid, 256>>>(x, out);
}

// round 6
// speedup vs baseline: 3.0554x; 2.1318x over previous
#include <cuda_runtime.h>
#include <cstdint>

// ---------------------------------------------------------------------------
// SESConv_H_H — TF32 warp-level mma.sync implicit conv.
//   D[o(16), pix] += Keff[o, (c,tap)] · X[(c,tap), pix] per (b, g, valid ij)
//   m16n8k8: M = 16 output channels, N = 8 pixels, K = 8 input channels.
// ---------------------------------------------------------------------------

#define SG    12
#define CIN   16
#define COUT  16
#define BATCH 8
#define HWD   128

#define TILE_W 32
#define TILE_H 16
#define HALO_W 36               // TILE_W + 4
#define HALO_H 20               // TILE_H + 4
#define PLANE_STRIDE 728        // 20*36 = 720, padded: 728 % 32 = 24 (bank spread)
#define XS_UINTS (CIN * PLANE_STRIDE)      // 11648
#define KS_UINTS 6400                      // 25 taps * 2 chunks * 128
#define SMEM_BYTES ((XS_UINTS + KS_UINTS) * 4)   // 72192 B

// Keff (tf32 bit patterns): [g][ij][tap*2+ch][o*8 + q*2 + s], c = ch*8 + q + 4*s
__device__ uint32_t g_keff[SG * 4 * 50 * 128];

__device__ __forceinline__ uint32_t tf32r(float v) {
    uint32_t r;
    asm("cvt.rna.tf32.f32 %0, %1;" : "=r"(r) : "f"(v));
    return r;
}

__device__ __forceinline__ void mma_tf32(float* d,
                                         uint32_t a0, uint32_t a1,
                                         uint32_t a2, uint32_t a3,
                                         uint32_t b0, uint32_t b1) {
    asm volatile(
        "mma.sync.aligned.m16n8k8.row.col.f32.tf32.tf32.f32 "
        "{%0,%1,%2,%3}, {%4,%5,%6,%7}, {%8,%9}, {%0,%1,%2,%3};"
        : "+f"(d[0]), "+f"(d[1]), "+f"(d[2]), "+f"(d[3])
        : "r"(a0), "r"(a1), "r"(a2), "r"(a3), "r"(b0), "r"(b1));
}

__global__ void build_keff_kernel(const float* __restrict__ weight,
                                  const float* __restrict__ basis) {
    const int total = SG * 4 * 50 * 128;
    int idx = blockIdx.x * blockDim.x + threadIdx.x;
    if (idx >= total) return;
    const int within = idx % 6400;
    const int gij    = idx / 6400;
    const int g  = gij / 4;
    const int ij = gij % 4;
    const int blk = within / 128;     // tap*2 + ch
    const int r   = within % 128;
    const int tap = blk >> 1;
    const int ch  = blk & 1;
    const int o   = r >> 3;
    const int q   = (r >> 1) & 3;
    const int s   = r & 1;
    const int c   = ch * 8 + q + 4 * s;
    float v = 0.f;
#pragma unroll
    for (int f = 0; f < 9; ++f)
        v += weight[((o * CIN + c) * 4 + ij) * 9 + f] *
             basis[(f * SG + g) * 25 + tap];
    g_keff[idx] = tf32r(v);
}

__global__ void __launch_bounds__(256, 2)
ses_mma_kernel(const float* __restrict__ x, float* __restrict__ out) {
    extern __shared__ uint32_t dyn[];
    uint32_t* xs = dyn;                 // 16 planes, 20x36 halo, stride 728
    uint32_t* ks = dyn + XS_UINTS;      // Keff stage: 6400

    const int tid  = threadIdx.x;
    const int w    = tid >> 5;          // warp 0..7 -> output rows 2w, 2w+1
    const int lane = tid & 31;
    const int grp  = lane >> 2;         // fragment "groupID"
    const int tig  = lane & 3;          // fragment "threadID in group"

    const int bz = blockIdx.z;
    const int b  = bz / SG;
    const int g  = bz % SG;
    const int nr = g / 3;
    const int ns = g % 3;
    const int tx0 = blockIdx.x * TILE_W;
    const int ty0 = blockIdx.y * TILE_H;

    int ijv[4];
    int nv = 0;
#pragma unroll
    for (int ij = 0; ij < 4; ++ij)
        if (ns + (ij & 1) < 3) ijv[nv++] = ij;

    float acc[2][4][4];
#pragma unroll
    for (int r = 0; r < 2; ++r)
#pragma unroll
        for (int cr = 0; cr < 4; ++cr)
#pragma unroll
            for (int q = 0; q < 4; ++q) acc[r][cr][q] = 0.f;

    for (int sIdx = 0; sIdx < nv; ++sIdx) {
        const int ij = ijv[sIdx];
        const int sp = ((nr + (ij >> 1)) & 3) * 3 + (ns + (ij & 1));

        // fill x tile: 16 planes x 720, converted to tf32
        for (int e = tid; e < CIN * 720; e += 256) {
            const int p   = e / 720;
            const int rem = e - p * 720;
            const int rr  = rem / 36;
            const int cc  = rem - rr * 36;
            const int gy = ty0 + rr - 2;
            const int gx = tx0 + cc - 2;
            float v = 0.f;
            if ((unsigned)gy < (unsigned)HWD && (unsigned)gx < (unsigned)HWD)
                v = __ldg(x + ((((size_t)b * CIN + p) * SG + sp) << 14) +
                          gy * HWD + gx);
            xs[p * PLANE_STRIDE + rr * 36 + cc] = tf32r(v);
        }
        // fill Keff stage
        const uint32_t* kp = g_keff + (size_t)(g * 4 + ij) * 6400;
        for (int e = tid; e < 6400; e += 256) ks[e] = kp[e];
        __syncthreads();

#pragma unroll 1
        for (int ky = 0; ky < 5; ++ky) {
#pragma unroll
            for (int kx = 0; kx < 5; ++kx) {
                const int tap = ky * 5 + kx;
#pragma unroll
                for (int ch = 0; ch < 2; ++ch) {
                    const uint32_t* ka =
                        ks + (tap * 2 + ch) * 128 + grp * 8 + tig * 2;
                    const uint2 A0 = *reinterpret_cast<const uint2*>(ka);      // a0, a2
                    const uint2 A1 = *reinterpret_cast<const uint2*>(ka + 64); // a1, a3
                    const uint32_t* pb =
                        xs + (ch * 8 + tig) * PLANE_STRIDE + grp + kx;
#pragma unroll
                    for (int r = 0; r < 2; ++r) {
                        const uint32_t* pr = pb + (2 * w + r + ky) * 36;
#pragma unroll
                        for (int cr = 0; cr < 4; ++cr) {
                            const uint32_t b0 = pr[cr * 8];
                            const uint32_t b1 = pr[cr * 8 + 4 * PLANE_STRIDE];
                            mma_tf32(acc[r][cr], A0.x, A1.x, A0.y, A1.y, b0, b1);
                        }
                    }
                }
            }
        }
        __syncthreads();
    }

    // epilogue: thread owns D[o=grp, px=2*tig+{0,1}] and D[o=grp+8, ...] per mma
#pragma unroll
    for (int r = 0; r < 2; ++r) {
        const int row = ty0 + 2 * w + r;
#pragma unroll
        for (int cr = 0; cr < 4; ++cr) {
            const int px = tx0 + cr * 8 + tig * 2;
            float* o0 = out + ((((size_t)b * COUT + grp)     * SG + g) << 14) +
                        row * HWD + px;
            float* o1 = out + ((((size_t)b * COUT + grp + 8) * SG + g) << 14) +
                        row * HWD + px;
            *reinterpret_cast<float2*>(o0) =
                make_float2(acc[r][cr][0], acc[r][cr][1]);
            *reinterpret_cast<float2*>(o1) =
                make_float2(acc[r][cr][2], acc[r][cr][3]);
        }
    }
}

extern "C" void kernel_launch(void* const* d_in, const int* in_sizes, int n_in,
                              void* d_out, int out_size) {
    const float* x      = (const float*)d_in[0];
    const float* weight = (const float*)d_in[1];
    const float* basis  = (const float*)d_in[2];
    float* out = (float*)d_out;

    const int total = SG * 4 * 50 * 128;
    build_keff_kernel<<<(total + 255) / 256, 256>>>(weight, basis);

    cudaFuncSetAttribute(ses_mma_kernel,
                         cudaFuncAttributeMaxDynamicSharedMemorySize,
                         SMEM_BYTES);
    dim3 grid(HWD / TILE_W, HWD / TILE_H, BATCH * SG);
    ses_mma_kernel<<<grid, 256, SMEM_BYTES>>>(x, out);
}